// round 1
// baseline (speedup 1.0000x reference)
#include <cuda_runtime.h>
#include <math.h>

#define DIMK   256
#define LATENT 1024
#define BB     128
#define TT     512

// ---------------------------------------------------------------------------
// GEMM1: out[t, b, :] = x[b, t, :] @ Wx + bias   (M=B*T=65536, K=256, N=1024)
// Row r = b*T + t. Classic SGEMM: BM=64, BN=64, BK=16, 256 threads, 4x4/thread.
// ---------------------------------------------------------------------------
__global__ void gemm1_kernel(const float* __restrict__ x,
                             const float* __restrict__ W,     // W_in; Wx = rows [0,256)
                             const float* __restrict__ bias,
                             float* __restrict__ out) {
    const int BM = 64, BN = 64, BK = 16;
    __shared__ float As[BK][BM];
    __shared__ float Bs[BK][BN];

    const int tile_n = blockIdx.x;        // 0..15
    const int tile_m = blockIdx.y;        // 0..1023
    const int tid = threadIdx.x;          // 0..255
    const int tx = tid & 15;              // N direction (4 cols each)
    const int ty = tid >> 4;              // M direction (4 rows each)

    const int row0 = tile_m * BM;
    const int col0 = tile_n * BN;

    // A load: one float4 per thread: m = tid/4, k = (tid%4)*4
    const int a_m = tid >> 2;
    const int a_k = (tid & 3) << 2;
    // B load: one float4 per thread: k = tid/16, n = (tid%16)*4
    const int b_k = tid >> 4;
    const int b_n = (tid & 15) << 2;

    float acc[4][4] = {};

    for (int k0 = 0; k0 < DIMK; k0 += BK) {
        float4 av = *reinterpret_cast<const float4*>(
            &x[(size_t)(row0 + a_m) * DIMK + k0 + a_k]);
        As[a_k + 0][a_m] = av.x;
        As[a_k + 1][a_m] = av.y;
        As[a_k + 2][a_m] = av.z;
        As[a_k + 3][a_m] = av.w;
        *reinterpret_cast<float4*>(&Bs[b_k][b_n]) =
            *reinterpret_cast<const float4*>(
                &W[(size_t)(k0 + b_k) * LATENT + col0 + b_n]);
        __syncthreads();

        #pragma unroll
        for (int k = 0; k < BK; ++k) {
            float a[4], b[4];
            #pragma unroll
            for (int i = 0; i < 4; ++i) a[i] = As[k][ty * 4 + i];
            #pragma unroll
            for (int j = 0; j < 4; ++j) b[j] = Bs[k][tx * 4 + j];
            #pragma unroll
            for (int i = 0; i < 4; ++i)
                #pragma unroll
                for (int j = 0; j < 4; ++j)
                    acc[i][j] += a[i] * b[j];
        }
        __syncthreads();
    }

    // Epilogue: add bias, scatter to [T, B, L] layout.
    float4 bv = *reinterpret_cast<const float4*>(&bias[col0 + tx * 4]);
    #pragma unroll
    for (int i = 0; i < 4; ++i) {
        int r  = row0 + ty * 4 + i;
        int bi = r >> 9;          // r / T   (T = 512)
        int ti = r & (TT - 1);    // r % T
        float4 c;
        c.x = acc[i][0] + bv.x;
        c.y = acc[i][1] + bv.y;
        c.z = acc[i][2] + bv.z;
        c.w = acc[i][3] + bv.w;
        *reinterpret_cast<float4*>(
            &out[((size_t)ti * BB + bi) * LATENT + col0 + tx * 4]) = c;
    }
}

// ---------------------------------------------------------------------------
// t = 0: out[0] = tanh(out[0])      (h_prev is zero)
// ---------------------------------------------------------------------------
__global__ void tanh0_kernel(float* __restrict__ out0) {
    int i = blockIdx.x * blockDim.x + threadIdx.x;
    out0[i] = tanhf(out0[i]);
}

// ---------------------------------------------------------------------------
// Step t: out_t = tanh(out_t + hprev @ Wh)
//   M=128, N=1024, K=1024. BM=16, BN=64, BK=32 -> grid (16, 8) = 128 CTAs,
//   256 threads, 1x4 outputs/thread. Wh (4 MB) lives in L2 across steps.
// ---------------------------------------------------------------------------
__global__ void step_kernel(const float* __restrict__ hprev,  // [B, L]
                            const float* __restrict__ Wh,     // [L, L]
                            float* __restrict__ out_t) {      // [B, L] (= xw_t + b on entry)
    const int BM = 16, BN = 64, BK = 32;
    __shared__ float As[BK][BM];
    __shared__ float Bs[BK][BN];

    const int tile_n = blockIdx.x;   // 0..15
    const int tile_m = blockIdx.y;   // 0..7
    const int tid = threadIdx.x;     // 0..255
    const int tx = tid & 15;         // N direction (4 cols)
    const int ty = tid >> 4;         // M direction (1 row)

    const int row0 = tile_m * BM;
    const int col0 = tile_n * BN;

    // A tile loads: 16x32 = 512 floats, float2 per thread.
    const int a_m = tid >> 4;              // 0..15
    const int a_k = (tid & 15) << 1;       // 0,2,..,30

    float acc[4] = {0.f, 0.f, 0.f, 0.f};

    for (int k0 = 0; k0 < LATENT; k0 += BK) {
        float2 av = *reinterpret_cast<const float2*>(
            &hprev[(size_t)(row0 + a_m) * LATENT + k0 + a_k]);
        As[a_k + 0][a_m] = av.x;
        As[a_k + 1][a_m] = av.y;

        // B tile: 32x64 = 2048 floats = 512 float4, 2 per thread.
        #pragma unroll
        for (int s = 0; s < 2; ++s) {
            int j  = tid + s * 256;
            int bk = j >> 4;
            int bn = (j & 15) << 2;
            *reinterpret_cast<float4*>(&Bs[bk][bn]) =
                *reinterpret_cast<const float4*>(
                    &Wh[(size_t)(k0 + bk) * LATENT + col0 + bn]);
        }
        __syncthreads();

        #pragma unroll
        for (int k = 0; k < BK; ++k) {
            float a = As[k][ty];
            float4 bv = *reinterpret_cast<const float4*>(&Bs[k][tx * 4]);
            acc[0] += a * bv.x;
            acc[1] += a * bv.y;
            acc[2] += a * bv.z;
            acc[3] += a * bv.w;
        }
        __syncthreads();
    }

    size_t o = (size_t)(row0 + ty) * LATENT + col0 + tx * 4;
    float4 c = *reinterpret_cast<const float4*>(&out_t[o]);
    c.x = tanhf(acc[0] + c.x);
    c.y = tanhf(acc[1] + c.y);
    c.z = tanhf(acc[2] + c.z);
    c.w = tanhf(acc[3] + c.w);
    *reinterpret_cast<float4*>(&out_t[o]) = c;
}

// ---------------------------------------------------------------------------
extern "C" void kernel_launch(void* const* d_in, const int* in_sizes, int n_in,
                              void* d_out, int out_size) {
    const float* x    = (const float*)d_in[0];   // [B, T, DIM]
    const float* W    = (const float*)d_in[1];   // [DIM+LATENT, LATENT]
    const float* bias = (const float*)d_in[2];   // [LATENT]
    float* out = (float*)d_out;                  // [T, B, LATENT]

    const float* Wh = W + (size_t)DIMK * LATENT;

    // 1) xw + bias staged into out[t, b, :]
    gemm1_kernel<<<dim3(16, 1024), 256>>>(x, W, bias, out);

    // 2) t = 0: h0 = 0 -> out[0] = tanh(out[0])
    tanh0_kernel<<<(BB * LATENT) / 256, 256>>>(out);

    // 3) sequential scan, in-place on out
    for (int t = 1; t < TT; ++t) {
        step_kernel<<<dim3(16, 8), 256>>>(
            out + (size_t)(t - 1) * BB * LATENT,
            Wh,
            out + (size_t)t * BB * LATENT);
    }
}